// round 1
// baseline (speedup 1.0000x reference)
#include <cuda_runtime.h>
#include <stdint.h>

#define BATCH 4
#define SEQ   2048
#define DIM   1024
#define NH    16
#define HD    64
#define SCALE 0.125f
#define MTOT  (BATCH*SEQ)

// ---- scratch (no cudaMalloc allowed) ----
__device__ float g_q[MTOT * DIM];                 // 32 MB
__device__ float g_k[MTOT * DIM];                 // 32 MB
__device__ float g_v[MTOT * DIM];                 // 32 MB
__device__ float g_ctx[MTOT * DIM];               // 32 MB
__device__ float g_r[(size_t)BATCH * SEQ * SEQ];  // 64 MB : 1/Z

// ---- helpers ----
__device__ __forceinline__ uint32_t f2tf(float x) {
    uint32_t u;
    asm("cvt.rna.tf32.f32 %0, %1;" : "=r"(u) : "f"(x));
    return u;
}
__device__ __forceinline__ uint4 cvt4(float4 v) {
    return make_uint4(f2tf(v.x), f2tf(v.y), f2tf(v.z), f2tf(v.w));
}
// D += A(16x8, row) * B(8x8, col)   tf32, fp32 accum
__device__ __forceinline__ void mma8(float c[4], const uint32_t a[4], const uint32_t b[2]) {
    asm volatile(
        "mma.sync.aligned.m16n8k8.row.col.f32.tf32.tf32.f32 "
        "{%0,%1,%2,%3}, {%4,%5,%6,%7}, {%8,%9}, {%0,%1,%2,%3};\n"
        : "+f"(c[0]), "+f"(c[1]), "+f"(c[2]), "+f"(c[3])
        : "r"(a[0]), "r"(a[1]), "r"(a[2]), "r"(a[3]), "r"(b[0]), "r"(b[1]));
}

// =====================================================================
// Generic GEMM: C[M,1024] = A[M,1024] @ W[1024,1024], all row-major fp32.
// 128x128 block tile, 256 threads, 8 warps (2m x 4n), warp tile 64x32.
// =====================================================================
__global__ __launch_bounds__(256) void gemm_tf32(const float* __restrict__ A,
                                                 const float* __restrict__ W,
                                                 float* __restrict__ C) {
    __shared__ uint32_t sA[128][36];   // stride%32==4 -> conflict-free A frags
    __shared__ uint32_t sB[32][136];   // stride%32==8 -> conflict-free B frags
    const int tid = threadIdx.x;
    const int m0 = blockIdx.y * 128;
    const int n0 = blockIdx.x * 128;
    const int w = tid >> 5, lane = tid & 31, g = lane >> 2, tg = lane & 3;
    const int wm = (w >> 2) * 64, wn = (w & 3) * 32;

    float acc[4][4][4];
#pragma unroll
    for (int i = 0; i < 4; i++)
#pragma unroll
        for (int j = 0; j < 4; j++)
#pragma unroll
            for (int e = 0; e < 4; e++) acc[i][j][e] = 0.f;

    const int ra = tid >> 3, ca = (tid & 7) << 2;
    const int rb = tid >> 5, cb = (tid & 31) << 2;

    for (int kt = 0; kt < DIM; kt += 32) {
#pragma unroll
        for (int i = 0; i < 4; i++) {
            float4 va = *(const float4*)(A + (size_t)(m0 + ra + 32 * i) * DIM + kt + ca);
            *(uint4*)&sA[ra + 32 * i][ca] = cvt4(va);
            float4 vb = *(const float4*)(W + (size_t)(kt + rb + 8 * i) * DIM + n0 + cb);
            *(uint4*)&sB[rb + 8 * i][cb] = cvt4(vb);
        }
        __syncthreads();
#pragma unroll
        for (int kk = 0; kk < 32; kk += 8) {
            uint32_t af[4][4], bf[4][2];
#pragma unroll
            for (int mt = 0; mt < 4; mt++) {
                int r = wm + mt * 16;
                af[mt][0] = sA[r + g][kk + tg];
                af[mt][1] = sA[r + g + 8][kk + tg];
                af[mt][2] = sA[r + g][kk + tg + 4];
                af[mt][3] = sA[r + g + 8][kk + tg + 4];
            }
#pragma unroll
            for (int nt = 0; nt < 4; nt++) {
                int nb = wn + nt * 8;
                bf[nt][0] = sB[kk + tg][nb + g];
                bf[nt][1] = sB[kk + tg + 4][nb + g];
            }
#pragma unroll
            for (int mt = 0; mt < 4; mt++)
#pragma unroll
                for (int nt = 0; nt < 4; nt++) mma8(acc[mt][nt], af[mt], bf[nt]);
        }
        __syncthreads();
    }
#pragma unroll
    for (int mt = 0; mt < 4; mt++)
#pragma unroll
        for (int nt = 0; nt < 4; nt++) {
            int row = m0 + wm + mt * 16 + g;
            int col = n0 + wn + nt * 8 + 2 * tg;
            *(float2*)(C + (size_t)row * DIM + col) = make_float2(acc[mt][nt][0], acc[mt][nt][1]);
            *(float2*)(C + (size_t)(row + 8) * DIM + col) = make_float2(acc[mt][nt][2], acc[mt][nt][3]);
        }
}

// =====================================================================
// Pass A: R[b,q,k] = 1 / sum_h exp(scale * q_h . k_h)
// CTA: one 128x128 (q,k) tile; loops 16 heads x (d=64 in two 32-chunks).
// =====================================================================
__global__ __launch_bounds__(256) void attn_z() {
    __shared__ uint32_t sQ[128][36];
    __shared__ uint32_t sK[128][36];
    const int tid = threadIdx.x;
    const int b = blockIdx.z, qt = blockIdx.y * 128, kt = blockIdx.x * 128;
    const int w = tid >> 5, lane = tid & 31, g = lane >> 2, tg = lane & 3;
    const int wm = (w >> 2) * 64, wn = (w & 3) * 32;
    const int ra = tid >> 3, ca = (tid & 7) << 2;

    const float* qb = g_q + (size_t)(b * SEQ + qt) * DIM;
    const float* kb = g_k + (size_t)(b * SEQ + kt) * DIM;

    float zacc[4][4][4];
#pragma unroll
    for (int i = 0; i < 4; i++)
#pragma unroll
        for (int j = 0; j < 4; j++)
#pragma unroll
            for (int e = 0; e < 4; e++) zacc[i][j][e] = 0.f;

    for (int h = 0; h < NH; h++) {
        float sacc[4][4][4];
#pragma unroll
        for (int i = 0; i < 4; i++)
#pragma unroll
            for (int j = 0; j < 4; j++)
#pragma unroll
                for (int e = 0; e < 4; e++) sacc[i][j][e] = 0.f;

#pragma unroll
        for (int dk = 0; dk < HD; dk += 32) {
#pragma unroll
            for (int i = 0; i < 4; i++) {
                float4 vq = *(const float4*)(qb + (size_t)(ra + 32 * i) * DIM + h * HD + dk + ca);
                *(uint4*)&sQ[ra + 32 * i][ca] = cvt4(vq);
                float4 vk = *(const float4*)(kb + (size_t)(ra + 32 * i) * DIM + h * HD + dk + ca);
                *(uint4*)&sK[ra + 32 * i][ca] = cvt4(vk);
            }
            __syncthreads();
#pragma unroll
            for (int kk = 0; kk < 32; kk += 8) {
                uint32_t af[4][4], bf[4][2];
#pragma unroll
                for (int mt = 0; mt < 4; mt++) {
                    int r = wm + mt * 16;
                    af[mt][0] = sQ[r + g][kk + tg];
                    af[mt][1] = sQ[r + g + 8][kk + tg];
                    af[mt][2] = sQ[r + g][kk + tg + 4];
                    af[mt][3] = sQ[r + g + 8][kk + tg + 4];
                }
#pragma unroll
                for (int nt = 0; nt < 4; nt++) {
                    int nb = wn + nt * 8;
                    bf[nt][0] = sK[nb + g][kk + tg];
                    bf[nt][1] = sK[nb + g][kk + tg + 4];
                }
#pragma unroll
                for (int mt = 0; mt < 4; mt++)
#pragma unroll
                    for (int nt = 0; nt < 4; nt++) mma8(sacc[mt][nt], af[mt], bf[nt]);
            }
            __syncthreads();
        }
#pragma unroll
        for (int i = 0; i < 4; i++)
#pragma unroll
            for (int j = 0; j < 4; j++)
#pragma unroll
                for (int e = 0; e < 4; e++) zacc[i][j][e] += __expf(sacc[i][j][e] * SCALE);
    }
#pragma unroll
    for (int mt = 0; mt < 4; mt++)
#pragma unroll
        for (int nt = 0; nt < 4; nt++) {
            int row = qt + wm + mt * 16 + g;
            int col = kt + wn + nt * 8 + 2 * tg;
            float* rp = g_r + ((size_t)b * SEQ + row) * SEQ + col;
            *(float2*)rp = make_float2(1.f / zacc[mt][nt][0], 1.f / zacc[mt][nt][1]);
            *(float2*)(rp + (size_t)8 * SEQ) = make_float2(1.f / zacc[mt][nt][2], 1.f / zacc[mt][nt][3]);
        }
}

// =====================================================================
// Pass B: ctx[b,q,h*64+d] = sum_k exp(scale*S)*R[b,q,k] * V[b,k,h*64+d]
// CTA: (b, h, 128 q-rows); loops k in 128-tiles. Dynamic smem.
// =====================================================================
#define SQ_STRIDE 68
#define SV_STRIDE 72
#define SP_STRIDE 132
#define PB_SMEM ((128 * SQ_STRIDE + 128 * SQ_STRIDE + 128 * SV_STRIDE + 128 * SP_STRIDE) * 4)

__global__ __launch_bounds__(256) void attn_ctx() {
    extern __shared__ uint32_t sm[];
    uint32_t* sQ = sm;
    uint32_t* sK = sQ + 128 * SQ_STRIDE;
    uint32_t* sV = sK + 128 * SQ_STRIDE;
    uint32_t* sP = sV + 128 * SV_STRIDE;

    const int tid = threadIdx.x;
    const int b = blockIdx.z, h = blockIdx.y, qt = blockIdx.x * 128;
    const int w = tid >> 5, lane = tid & 31, g = lane >> 2, tg = lane & 3;
    const int wm = (w >> 2) * 64, wn = (w & 3) * 32;  // GEMM1 (128x128)
    const int wn2 = (w & 3) * 16;                     // GEMM2 n (64)
    const int rl = tid >> 4, cl = (tid & 15) << 2;

    const float* qb = g_q + (size_t)(b * SEQ + qt) * DIM + h * HD;
#pragma unroll
    for (int i = 0; i < 8; i++) {
        float4 vq = *(const float4*)(qb + (size_t)(rl + 16 * i) * DIM + cl);
        *(uint4*)&sQ[(rl + 16 * i) * SQ_STRIDE + cl] = cvt4(vq);
    }

    float cacc[4][2][4];
#pragma unroll
    for (int i = 0; i < 4; i++)
#pragma unroll
        for (int j = 0; j < 2; j++)
#pragma unroll
            for (int e = 0; e < 4; e++) cacc[i][j][e] = 0.f;

    for (int kt = 0; kt < SEQ; kt += 128) {
        const float* kbp = g_k + (size_t)(b * SEQ + kt) * DIM + h * HD;
        const float* vbp = g_v + (size_t)(b * SEQ + kt) * DIM + h * HD;
#pragma unroll
        for (int i = 0; i < 8; i++) {
            float4 vk = *(const float4*)(kbp + (size_t)(rl + 16 * i) * DIM + cl);
            *(uint4*)&sK[(rl + 16 * i) * SQ_STRIDE + cl] = cvt4(vk);
            float4 vv = *(const float4*)(vbp + (size_t)(rl + 16 * i) * DIM + cl);
            *(uint4*)&sV[(rl + 16 * i) * SV_STRIDE + cl] = cvt4(vv);
        }
        __syncthreads();

        // GEMM1: S = Q @ K^T  (128x128, contraction 64)
        float sacc[4][4][4];
#pragma unroll
        for (int i = 0; i < 4; i++)
#pragma unroll
            for (int j = 0; j < 4; j++)
#pragma unroll
                for (int e = 0; e < 4; e++) sacc[i][j][e] = 0.f;
#pragma unroll
        for (int kk = 0; kk < 64; kk += 8) {
            uint32_t af[4][4], bf[4][2];
#pragma unroll
            for (int mt = 0; mt < 4; mt++) {
                int r = wm + mt * 16;
                af[mt][0] = sQ[(r + g) * SQ_STRIDE + kk + tg];
                af[mt][1] = sQ[(r + g + 8) * SQ_STRIDE + kk + tg];
                af[mt][2] = sQ[(r + g) * SQ_STRIDE + kk + tg + 4];
                af[mt][3] = sQ[(r + g + 8) * SQ_STRIDE + kk + tg + 4];
            }
#pragma unroll
            for (int nt = 0; nt < 4; nt++) {
                int nb = wn + nt * 8;
                bf[nt][0] = sK[(nb + g) * SQ_STRIDE + kk + tg];
                bf[nt][1] = sK[(nb + g) * SQ_STRIDE + kk + tg + 4];
            }
#pragma unroll
            for (int mt = 0; mt < 4; mt++)
#pragma unroll
                for (int nt = 0; nt < 4; nt++) mma8(sacc[mt][nt], af[mt], bf[nt]);
        }

        // P = exp(scale*S) * R  -> smem (tf32)
#pragma unroll
        for (int mt = 0; mt < 4; mt++)
#pragma unroll
            for (int nt = 0; nt < 4; nt++) {
                int row = wm + mt * 16 + g;
                int col = wn + nt * 8 + 2 * tg;
                const float* rp = g_r + ((size_t)b * SEQ + qt + row) * SEQ + kt + col;
                float2 r0 = *(const float2*)rp;
                float2 r1 = *(const float2*)(rp + (size_t)8 * SEQ);
                sP[row * SP_STRIDE + col] = f2tf(__expf(sacc[mt][nt][0] * SCALE) * r0.x);
                sP[row * SP_STRIDE + col + 1] = f2tf(__expf(sacc[mt][nt][1] * SCALE) * r0.y);
                sP[(row + 8) * SP_STRIDE + col] = f2tf(__expf(sacc[mt][nt][2] * SCALE) * r1.x);
                sP[(row + 8) * SP_STRIDE + col + 1] = f2tf(__expf(sacc[mt][nt][3] * SCALE) * r1.y);
            }
        __syncthreads();

        // GEMM2: ctx += P @ V  (128x64, contraction 128)
#pragma unroll
        for (int kk = 0; kk < 128; kk += 8) {
            uint32_t af[4][4], bf[2][2];
#pragma unroll
            for (int mt = 0; mt < 4; mt++) {
                int r = wm + mt * 16;
                af[mt][0] = sP[(r + g) * SP_STRIDE + kk + tg];
                af[mt][1] = sP[(r + g + 8) * SP_STRIDE + kk + tg];
                af[mt][2] = sP[(r + g) * SP_STRIDE + kk + tg + 4];
                af[mt][3] = sP[(r + g + 8) * SP_STRIDE + kk + tg + 4];
            }
#pragma unroll
            for (int nt = 0; nt < 2; nt++) {
                int nb = wn2 + nt * 8;
                bf[nt][0] = sV[(kk + tg) * SV_STRIDE + nb + g];
                bf[nt][1] = sV[(kk + tg + 4) * SV_STRIDE + nb + g];
            }
#pragma unroll
            for (int mt = 0; mt < 4; mt++)
#pragma unroll
                for (int nt = 0; nt < 2; nt++) mma8(cacc[mt][nt], af[mt], bf[nt]);
        }
        __syncthreads();
    }

    float* cb = g_ctx + (size_t)(b * SEQ + qt) * DIM + h * HD;
#pragma unroll
    for (int mt = 0; mt < 4; mt++)
#pragma unroll
        for (int nt = 0; nt < 2; nt++) {
            int row = wm + mt * 16 + g;
            int col = wn2 + nt * 8 + 2 * tg;
            *(float2*)(cb + (size_t)row * DIM + col) = make_float2(cacc[mt][nt][0], cacc[mt][nt][1]);
            *(float2*)(cb + (size_t)(row + 8) * DIM + col) = make_float2(cacc[mt][nt][2], cacc[mt][nt][3]);
        }
}

// =====================================================================
extern "C" void kernel_launch(void* const* d_in, const int* in_sizes, int n_in,
                              void* d_out, int out_size) {
    const float* x = (const float*)d_in[0];
    const float* wq = (const float*)d_in[1];
    const float* wk = (const float*)d_in[2];
    const float* wv = (const float*)d_in[3];
    const float* wo = (const float*)d_in[4];
    float* out = (float*)d_out;

    float *q, *k, *v, *ctx;
    cudaGetSymbolAddress((void**)&q, g_q);
    cudaGetSymbolAddress((void**)&k, g_k);
    cudaGetSymbolAddress((void**)&v, g_v);
    cudaGetSymbolAddress((void**)&ctx, g_ctx);

    dim3 gg(DIM / 128, MTOT / 128);  // (8, 64)
    gemm_tf32<<<gg, 256>>>(x, wq, q);
    gemm_tf32<<<gg, 256>>>(x, wk, k);
    gemm_tf32<<<gg, 256>>>(x, wv, v);

    attn_z<<<dim3(SEQ / 128, SEQ / 128, BATCH), 256>>>();

    cudaFuncSetAttribute(attn_ctx, cudaFuncAttributeMaxDynamicSharedMemorySize, PB_SMEM);
    attn_ctx<<<dim3(SEQ / 128, NH, BATCH), 256, PB_SMEM>>>();

    gemm_tf32<<<gg, 256>>>(ctx, wo, out);
}